// round 2
// baseline (speedup 1.0000x reference)
#include <cuda_runtime.h>

#define NNODES 50000
#define NEDGES 800000
// channels: IN=64, EDGE=32, OUT=64, d_in = 160

// Scratch (allocation-free rule: __device__ globals)
__device__ float g_AB[(size_t)NNODES * 128];   // [n][0:64]=x@W1a, [64:128]=x@W1b
__device__ float g_cnt[NNODES];

// ---------------------------------------------------------------------------
// init: zero output accumulator + counts (d_out is poisoned by harness)
// ---------------------------------------------------------------------------
__global__ void init_kernel(float* __restrict__ out) {
    int stride = gridDim.x * blockDim.x;
    for (int i = blockIdx.x * blockDim.x + threadIdx.x; i < NNODES * 16; i += stride)
        ((float4*)out)[i] = make_float4(0.f, 0.f, 0.f, 0.f);
    for (int i = blockIdx.x * blockDim.x + threadIdx.x; i < NNODES; i += stride)
        g_cnt[i] = 0.0f;
}

// ---------------------------------------------------------------------------
// node GEMM: AB[n][c'] = sum_k x[n][k] * Wn[k][c']
//   Wn[k][c'] = W1[k][c']        for c' < 64   (row-part, applied to x[row])
//             = W1[64+k][c'-64]  for c' >= 64  (col-part, applied to x[col])
// 32 nodes x 128 ch per block, 256 threads, 4x4 micro-tile
// ---------------------------------------------------------------------------
__global__ __launch_bounds__(256) void node_gemm_kernel(
    const float* __restrict__ x, const float* __restrict__ W1)
{
    __shared__ float s_x[32 * 65];
    __shared__ float s_W[64 * 128];

    int tid = threadIdx.x;
    int n_base = blockIdx.x * 32;

    for (int idx = tid; idx < 64 * 128; idx += 256) {
        int k = idx >> 7, c = idx & 127;
        s_W[idx] = (c < 64) ? W1[k * 64 + c] : W1[(64 + k) * 64 + (c - 64)];
    }
    for (int idx = tid; idx < 32 * 64; idx += 256) {
        int n = idx >> 6, k = idx & 63;
        int gn = n_base + n;
        s_x[n * 65 + k] = (gn < NNODES) ? x[(size_t)gn * 64 + k] : 0.0f;
    }
    __syncthreads();

    int tr = tid >> 5, tc = tid & 31;   // warp spans one tr -> a-loads broadcast
    int n0 = tr * 4, c0 = tc * 4;

    float acc[4][4] = {};
#pragma unroll 16
    for (int k = 0; k < 64; k++) {
        float a[4];
#pragma unroll
        for (int i = 0; i < 4; i++) a[i] = s_x[(n0 + i) * 65 + k];
        float4 b = *(const float4*)&s_W[k * 128 + c0];
#pragma unroll
        for (int i = 0; i < 4; i++) {
            acc[i][0] = fmaf(a[i], b.x, acc[i][0]);
            acc[i][1] = fmaf(a[i], b.y, acc[i][1]);
            acc[i][2] = fmaf(a[i], b.z, acc[i][2]);
            acc[i][3] = fmaf(a[i], b.w, acc[i][3]);
        }
    }
#pragma unroll
    for (int i = 0; i < 4; i++) {
        int gn = n_base + n0 + i;
        if (gn < NNODES) {
            float4 v = make_float4(acc[i][0], acc[i][1], acc[i][2], acc[i][3]);
            *(float4*)&g_AB[(size_t)gn * 128 + c0] = v;
        }
    }
}

// ---------------------------------------------------------------------------
// vectorized scatter-add: red.global.add.v4.f32 (sm_90+), 4x fewer RED ops
// ---------------------------------------------------------------------------
__device__ __forceinline__ void red_add_v4(float* addr, float a, float b,
                                           float c, float d) {
    asm volatile("red.global.add.v4.f32 [%0], {%1, %2, %3, %4};"
                 :: "l"(addr), "f"(a), "f"(b), "f"(c), "f"(d)
                 : "memory");
}

// ---------------------------------------------------------------------------
// edge kernel: per block = 64 edges, 128 threads, 4-edge x 8-col micro-tiles.
//   C  = ea @ W1c                      (64x64 GEMM, K=32)
//   h  = relu(C + AB[row][0:64] + AB[col][64:128] + b1)
//   m  = h @ W2 + b2                   (K=64)
//   red.add into out[col], count++
// ---------------------------------------------------------------------------
__global__ __launch_bounds__(128) void edge_kernel(
    const int*   __restrict__ ei,   // [2*E], row then col
    const float* __restrict__ ea,   // [E,32]
    const float* __restrict__ W1,   // [160,64]
    const float* __restrict__ b1,   // [64]
    const float* __restrict__ W2,   // [64,64]
    const float* __restrict__ b2,   // [64]
    float*       __restrict__ out)  // [N,64] accumulator
{
    __shared__ float s_W1c[32 * 64];    //  8 KB
    __shared__ float s_W2[64 * 64];     // 16 KB
    __shared__ float s_h[64 * 65];      // 16.6 KB; phase 1 aliased as s_ea[64*33]
    __shared__ int   s_row[64], s_col[64];

    float* s_ea = s_h;                  // 2112 floats <= 4160, safe alias

    int tid = threadIdx.x;
    int e_base = blockIdx.x * 64;

    if (tid < 64) {
        s_row[tid] = ei[e_base + tid];
        int c = ei[NEDGES + e_base + tid];
        s_col[tid] = c;
        atomicAdd(&g_cnt[c], 1.0f);     // one count per edge
    }
    // W1c = rows 128..159 of W1 (contiguous 2048 floats)
    for (int idx = tid; idx < 32 * 64; idx += 128)
        s_W1c[idx] = W1[128 * 64 + idx];
    for (int idx = tid; idx < 64 * 64; idx += 128)
        s_W2[idx] = W2[idx];
    for (int idx = tid; idx < 64 * 32; idx += 128) {
        int e = idx >> 5, k = idx & 31;
        s_ea[e * 33 + k] = ea[(size_t)(e_base + e) * 32 + k];
    }
    __syncthreads();

    int er = tid >> 3, cr = tid & 7;    // 16 er x 8 cr
    int e0 = er * 4, c0 = cr * 8;

    // ---- GEMM1: C = ea @ W1c, K=32 (1.5 B LDS per FMA) ----
    float acc[4][8] = {};
#pragma unroll
    for (int k = 0; k < 32; k++) {
        float a[4];
#pragma unroll
        for (int i = 0; i < 4; i++) a[i] = s_ea[(e0 + i) * 33 + k];
        float4 bL = *(const float4*)&s_W1c[k * 64 + c0];
        float4 bR = *(const float4*)&s_W1c[k * 64 + c0 + 4];
#pragma unroll
        for (int i = 0; i < 4; i++) {
            acc[i][0] = fmaf(a[i], bL.x, acc[i][0]);
            acc[i][1] = fmaf(a[i], bL.y, acc[i][1]);
            acc[i][2] = fmaf(a[i], bL.z, acc[i][2]);
            acc[i][3] = fmaf(a[i], bL.w, acc[i][3]);
            acc[i][4] = fmaf(a[i], bR.x, acc[i][4]);
            acc[i][5] = fmaf(a[i], bR.y, acc[i][5]);
            acc[i][6] = fmaf(a[i], bR.z, acc[i][6]);
            acc[i][7] = fmaf(a[i], bR.w, acc[i][7]);
        }
    }
    __syncthreads();   // done reading s_ea; region becomes s_h

    // ---- epilogue 1: gather node terms, bias, relu -> s_h ----
    float4 b1L = *(const float4*)&b1[c0];
    float4 b1R = *(const float4*)&b1[c0 + 4];
#pragma unroll
    for (int i = 0; i < 4; i++) {
        int e = e0 + i;
        const float* pr = &g_AB[(size_t)s_row[e] * 128 + c0];
        const float* pc = &g_AB[(size_t)s_col[e] * 128 + 64 + c0];
        float4 avL = *(const float4*)pr;
        float4 avR = *(const float4*)(pr + 4);
        float4 bvL = *(const float4*)pc;
        float4 bvR = *(const float4*)(pc + 4);
        float* hp = &s_h[e * 65 + c0];
        hp[0] = fmaxf(acc[i][0] + avL.x + bvL.x + b1L.x, 0.0f);
        hp[1] = fmaxf(acc[i][1] + avL.y + bvL.y + b1L.y, 0.0f);
        hp[2] = fmaxf(acc[i][2] + avL.z + bvL.z + b1L.z, 0.0f);
        hp[3] = fmaxf(acc[i][3] + avL.w + bvL.w + b1L.w, 0.0f);
        hp[4] = fmaxf(acc[i][4] + avR.x + bvR.x + b1R.x, 0.0f);
        hp[5] = fmaxf(acc[i][5] + avR.y + bvR.y + b1R.y, 0.0f);
        hp[6] = fmaxf(acc[i][6] + avR.z + bvR.z + b1R.z, 0.0f);
        hp[7] = fmaxf(acc[i][7] + avR.w + bvR.w + b1R.w, 0.0f);
    }
    __syncthreads();

    // ---- GEMM2: m = h @ W2, K=64 ----
    float acc2[4][8] = {};
#pragma unroll 8
    for (int k = 0; k < 64; k++) {
        float a[4];
#pragma unroll
        for (int i = 0; i < 4; i++) a[i] = s_h[(e0 + i) * 65 + k];
        float4 bL = *(const float4*)&s_W2[k * 64 + c0];
        float4 bR = *(const float4*)&s_W2[k * 64 + c0 + 4];
#pragma unroll
        for (int i = 0; i < 4; i++) {
            acc2[i][0] = fmaf(a[i], bL.x, acc2[i][0]);
            acc2[i][1] = fmaf(a[i], bL.y, acc2[i][1]);
            acc2[i][2] = fmaf(a[i], bL.z, acc2[i][2]);
            acc2[i][3] = fmaf(a[i], bL.w, acc2[i][3]);
            acc2[i][4] = fmaf(a[i], bR.x, acc2[i][4]);
            acc2[i][5] = fmaf(a[i], bR.y, acc2[i][5]);
            acc2[i][6] = fmaf(a[i], bR.z, acc2[i][6]);
            acc2[i][7] = fmaf(a[i], bR.w, acc2[i][7]);
        }
    }

    // ---- epilogue 2: + b2, vectorized scatter-add to destination nodes ----
    float4 b2L = *(const float4*)&b2[c0];
    float4 b2R = *(const float4*)&b2[c0 + 4];
#pragma unroll
    for (int i = 0; i < 4; i++) {
        int dst = s_col[e0 + i];
        float* o = &out[(size_t)dst * 64 + c0];
        red_add_v4(o,     acc2[i][0] + b2L.x, acc2[i][1] + b2L.y,
                          acc2[i][2] + b2L.z, acc2[i][3] + b2L.w);
        red_add_v4(o + 4, acc2[i][4] + b2R.x, acc2[i][5] + b2R.y,
                          acc2[i][6] + b2R.z, acc2[i][7] + b2R.w);
    }
}

// ---------------------------------------------------------------------------
// finalize: mean division with count clipped to >= 1 (vectorized)
// ---------------------------------------------------------------------------
__global__ void finalize_kernel(float* __restrict__ out) {
    int stride = gridDim.x * blockDim.x;
    for (int i = blockIdx.x * blockDim.x + threadIdx.x; i < NNODES * 16; i += stride) {
        float inv = 1.0f / fmaxf(g_cnt[i >> 4], 1.0f);
        float4 v = ((float4*)out)[i];
        v.x *= inv; v.y *= inv; v.z *= inv; v.w *= inv;
        ((float4*)out)[i] = v;
    }
}

// ---------------------------------------------------------------------------
extern "C" void kernel_launch(void* const* d_in, const int* in_sizes, int n_in,
                              void* d_out, int out_size)
{
    const float* x  = (const float*)d_in[0];
    const int*   ei = (const int*)  d_in[1];
    const float* ea = (const float*)d_in[2];
    const float* W1 = (const float*)d_in[3];
    const float* b1 = (const float*)d_in[4];
    const float* W2 = (const float*)d_in[5];
    const float* b2 = (const float*)d_in[6];
    float* out = (float*)d_out;

    init_kernel<<<592, 256>>>(out);
    node_gemm_kernel<<<(NNODES + 31) / 32, 256>>>(x, W1);
    edge_kernel<<<NEDGES / 64, 128>>>(ei, ea, W1, b1, W2, b2, out);
    finalize_kernel<<<592, 256>>>(out);
}

// round 15
// speedup vs baseline: 1.7362x; 1.7362x over previous
#include <cuda_runtime.h>

#define NNODES 50000
#define NEDGES 800000
// channels: IN=64, EDGE=32, OUT=64, d_in = 160

// Scratch (allocation-free rule: __device__ globals)
__device__ float g_AB[(size_t)NNODES * 128];   // [n][0:64]=x@W1a, [64:128]=x@W1b
__device__ float g_cnt[NNODES];

// ---------------------------------------------------------------------------
// helpers
// ---------------------------------------------------------------------------
__device__ __forceinline__ unsigned f2tf32(float f) {
    unsigned r;
    asm("cvt.rna.tf32.f32 %0, %1;" : "=r"(r) : "f"(f));
    return r;
}

__device__ __forceinline__ void mma_tf32(float c[4],
                                         unsigned a0, unsigned a1,
                                         unsigned a2, unsigned a3,
                                         unsigned b0, unsigned b1) {
    asm volatile(
        "mma.sync.aligned.m16n8k8.row.col.f32.tf32.tf32.f32 "
        "{%0,%1,%2,%3}, {%4,%5,%6,%7}, {%8,%9}, {%0,%1,%2,%3};"
        : "+f"(c[0]), "+f"(c[1]), "+f"(c[2]), "+f"(c[3])
        : "r"(a0), "r"(a1), "r"(a2), "r"(a3), "r"(b0), "r"(b1));
}

__device__ __forceinline__ void red_add_v4(float* addr, float a, float b,
                                           float c, float d) {
    asm volatile("red.global.add.v4.f32 [%0], {%1, %2, %3, %4};"
                 :: "l"(addr), "f"(a), "f"(b), "f"(c), "f"(d)
                 : "memory");
}

// ---------------------------------------------------------------------------
// init: zero output accumulator + counts (d_out is poisoned by harness)
// ---------------------------------------------------------------------------
__global__ void init_kernel(float* __restrict__ out) {
    int stride = gridDim.x * blockDim.x;
    for (int i = blockIdx.x * blockDim.x + threadIdx.x; i < NNODES * 16; i += stride)
        ((float4*)out)[i] = make_float4(0.f, 0.f, 0.f, 0.f);
    for (int i = blockIdx.x * blockDim.x + threadIdx.x; i < NNODES; i += stride)
        g_cnt[i] = 0.0f;
}

// ---------------------------------------------------------------------------
// node GEMM (fp32, exact): AB[n][c'] = sum_k x[n][k] * Wn[k][c']
//   Wn[k][c'] = W1[k][c'] (c'<64, row-part) / W1[64+k][c'-64] (col-part)
// ---------------------------------------------------------------------------
__global__ __launch_bounds__(256) void node_gemm_kernel(
    const float* __restrict__ x, const float* __restrict__ W1)
{
    __shared__ float s_x[32 * 65];
    __shared__ float s_W[64 * 128];

    int tid = threadIdx.x;
    int n_base = blockIdx.x * 32;

    for (int idx = tid; idx < 64 * 128; idx += 256) {
        int k = idx >> 7, c = idx & 127;
        s_W[idx] = (c < 64) ? W1[k * 64 + c] : W1[(64 + k) * 64 + (c - 64)];
    }
    for (int idx = tid; idx < 32 * 64; idx += 256) {
        int n = idx >> 6, k = idx & 63;
        int gn = n_base + n;
        s_x[n * 65 + k] = (gn < NNODES) ? x[(size_t)gn * 64 + k] : 0.0f;
    }
    __syncthreads();

    int tr = tid >> 5, tc = tid & 31;
    int n0 = tr * 4, c0 = tc * 4;

    float acc[4][4] = {};
#pragma unroll 16
    for (int k = 0; k < 64; k++) {
        float a[4];
#pragma unroll
        for (int i = 0; i < 4; i++) a[i] = s_x[(n0 + i) * 65 + k];
        float4 b = *(const float4*)&s_W[k * 128 + c0];
#pragma unroll
        for (int i = 0; i < 4; i++) {
            acc[i][0] = fmaf(a[i], b.x, acc[i][0]);
            acc[i][1] = fmaf(a[i], b.y, acc[i][1]);
            acc[i][2] = fmaf(a[i], b.z, acc[i][2]);
            acc[i][3] = fmaf(a[i], b.w, acc[i][3]);
        }
    }
#pragma unroll
    for (int i = 0; i < 4; i++) {
        int gn = n_base + n0 + i;
        if (gn < NNODES) {
            float4 v = make_float4(acc[i][0], acc[i][1], acc[i][2], acc[i][3]);
            *(float4*)&g_AB[(size_t)gn * 128 + c0] = v;
        }
    }
}

// ---------------------------------------------------------------------------
// edge kernel (tf32 tensor cores): 128 edges / block, 256 threads (8 warps).
// Warp w handles edges [w*16, w*16+16) x all 64 output cols via m16n8k8 mma.
//   GEMM1: C = ea @ W1c (K=32)   [tf32]
//   h = relu(C + AB[row][0:64] + AB[col][64:128] + b1)   [fp32 exact adds]
//   GEMM2: m = h @ W2 + b2 (K=64) [tf32]
//   scatter: red.global.add.v4 to out[col], + per-edge count
//
// SMEM strides chosen == 4 (mod 32) so all mma fragment loads hit 32 distinct
// banks: bank = (4*n + k) mod 32 with gid in [0,8), tig in [0,4).
// ---------------------------------------------------------------------------
#define EB 128                      // edges per block
#define SW1 36                      // stride of [n][k] W1c tile (k<32) and ea
#define SW2 68                      // stride of [n][k] W2 tile and h (k<64)
#define SM_W1C_OFF 0                            // 64*36 u32
#define SM_W2_OFF  (64 * SW1)                   // 64*68 u32
#define SM_H_OFF   (SM_W2_OFF + 64 * SW2)       // 128*68 u32 (aliases ea 128*36)
#define SM_IDX_OFF (SM_H_OFF + EB * SW2)        // 2*128 ints
#define SM_WORDS   (SM_IDX_OFF + 2 * EB)

__global__ __launch_bounds__(256) void edge_kernel(
    const int*   __restrict__ ei,   // [2*E], row then col
    const float* __restrict__ ea,   // [E,32]
    const float* __restrict__ W1,   // [160,64]
    const float* __restrict__ bias1,// [64]
    const float* __restrict__ W2,   // [64,64]
    const float* __restrict__ bias2,// [64]
    float*       __restrict__ out)  // [N,64] accumulator
{
    extern __shared__ unsigned smem[];
    unsigned* u_W1c = smem + SM_W1C_OFF;
    unsigned* u_W2  = smem + SM_W2_OFF;
    unsigned* u_h   = smem + SM_H_OFF;      // tf32 h operand / fp32 m buffer
    unsigned* u_ea  = smem + SM_H_OFF;      // alias (phase 1)
    int*      s_row = (int*)(smem + SM_IDX_OFF);
    int*      s_col = s_row + EB;

    int tid = threadIdx.x;
    int e_base = blockIdx.x * EB;

    // ---- stage indices + counts ----
    if (tid < EB) {
        s_row[tid] = ei[e_base + tid];
        int c = ei[NEDGES + e_base + tid];
        s_col[tid] = c;
        atomicAdd(&g_cnt[c], 1.0f);
    }
    // ---- stage W1c (rows 128..159 of W1), transposed [n][k], tf32 ----
    for (int idx = tid; idx < 32 * 64; idx += 256) {
        int k = idx >> 6, n = idx & 63;
        u_W1c[n * SW1 + k] = f2tf32(W1[128 * 64 + idx]);
    }
    // ---- stage W2 transposed [n][k], tf32 ----
    for (int idx = tid; idx < 64 * 64; idx += 256) {
        int k = idx >> 6, n = idx & 63;
        u_W2[n * SW2 + k] = f2tf32(W2[idx]);
    }
    // ---- stage ea [e][k] tf32 (float4 global reads) ----
    for (int idx4 = tid; idx4 < EB * 8; idx4 += 256) {
        int e = idx4 >> 3, k4 = (idx4 & 7) * 4;
        float4 v = *(const float4*)&ea[(size_t)(e_base + e) * 32 + k4];
        unsigned* p = &u_ea[e * SW1 + k4];
        p[0] = f2tf32(v.x); p[1] = f2tf32(v.y);
        p[2] = f2tf32(v.z); p[3] = f2tf32(v.w);
    }
    __syncthreads();

    int lane = tid & 31;
    int gid = lane >> 2;      // 0..7  (row within tile / col within B tile)
    int tig = lane & 3;       // 0..3  (k within fragment)
    int me0 = (tid >> 5) * 16;  // warp's edge base (8 warps x 16 edges)

    int le1 = me0 + gid;      // this thread's two edge rows
    int le2 = le1 + 8;

    // ---- GEMM1: C1 = ea @ W1c, K=32, acc[nt][4] over 8 n-tiles ----
    float c1[8][4] = {};
#pragma unroll
    for (int k0 = 0; k0 < 32; k0 += 8) {
        unsigned a0 = u_ea[le1 * SW1 + k0 + tig];
        unsigned a1 = u_ea[le2 * SW1 + k0 + tig];
        unsigned a2 = u_ea[le1 * SW1 + k0 + tig + 4];
        unsigned a3 = u_ea[le2 * SW1 + k0 + tig + 4];
#pragma unroll
        for (int nt = 0; nt < 8; nt++) {
            unsigned b0 = u_W1c[(nt * 8 + gid) * SW1 + k0 + tig];
            unsigned b1 = u_W1c[(nt * 8 + gid) * SW1 + k0 + tig + 4];
            mma_tf32(c1[nt], a0, a1, a2, a3, b0, b1);
        }
    }
    __syncthreads();   // all warps done reading u_ea; region becomes u_h

    // ---- epilogue 1: + AB gathers + bias, relu, store tf32 h ----
    {
        int r1 = s_row[le1], r2 = s_row[le2];
        int d1 = s_col[le1], d2 = s_col[le2];
#pragma unroll
        for (int nt = 0; nt < 8; nt++) {
            int col = nt * 8 + 2 * tig;
            float2 bb = *(const float2*)&bias1[col];
            float2 ar1 = *(const float2*)&g_AB[(size_t)r1 * 128 + col];
            float2 ac1 = *(const float2*)&g_AB[(size_t)d1 * 128 + 64 + col];
            float2 ar2 = *(const float2*)&g_AB[(size_t)r2 * 128 + col];
            float2 ac2 = *(const float2*)&g_AB[(size_t)d2 * 128 + 64 + col];
            u_h[le1 * SW2 + col]     = f2tf32(fmaxf(c1[nt][0] + ar1.x + ac1.x + bb.x, 0.f));
            u_h[le1 * SW2 + col + 1] = f2tf32(fmaxf(c1[nt][1] + ar1.y + ac1.y + bb.y, 0.f));
            u_h[le2 * SW2 + col]     = f2tf32(fmaxf(c1[nt][2] + ar2.x + ac2.x + bb.x, 0.f));
            u_h[le2 * SW2 + col + 1] = f2tf32(fmaxf(c1[nt][3] + ar2.y + ac2.y + bb.y, 0.f));
        }
    }
    __syncthreads();

    // ---- GEMM2: M = h @ W2, K=64 ----
    float c2[8][4] = {};
#pragma unroll
    for (int k0 = 0; k0 < 64; k0 += 8) {
        unsigned a0 = u_h[le1 * SW2 + k0 + tig];
        unsigned a1 = u_h[le2 * SW2 + k0 + tig];
        unsigned a2 = u_h[le1 * SW2 + k0 + tig + 4];
        unsigned a3 = u_h[le2 * SW2 + k0 + tig + 4];
#pragma unroll
        for (int nt = 0; nt < 8; nt++) {
            unsigned b0 = u_W2[(nt * 8 + gid) * SW2 + k0 + tig];
            unsigned b1 = u_W2[(nt * 8 + gid) * SW2 + k0 + tig + 4];
            mma_tf32(c2[nt], a0, a1, a2, a3, b0, b1);
        }
    }
    __syncthreads();   // all warps done reading u_h as GEMM2 operand

    // ---- epilogue 2a: m = C2 + b2 -> smem (fp32), mma layout ----
    {
        float* f_m = (float*)u_h;
#pragma unroll
        for (int nt = 0; nt < 8; nt++) {
            int col = nt * 8 + 2 * tig;
            float2 bb = *(const float2*)&bias2[col];
            f_m[le1 * SW2 + col]     = c2[nt][0] + bb.x;
            f_m[le1 * SW2 + col + 1] = c2[nt][1] + bb.y;
            f_m[le2 * SW2 + col]     = c2[nt][2] + bb.x;
            f_m[le2 * SW2 + col + 1] = c2[nt][3] + bb.y;
        }
    }
    __syncthreads();

    // ---- epilogue 2b: vectorized scatter (8 x red.v4 per thread) ----
    {
        const float* f_m = (const float*)u_h;
        int e = tid >> 1, half = (tid & 1) * 32;
        int dst = s_col[e];
        float* o = &out[(size_t)dst * 64 + half];
        const float* src = &f_m[e * SW2 + half];
#pragma unroll
        for (int j = 0; j < 8; j++) {
            float4 v = *(const float4*)&src[4 * j];
            red_add_v4(o + 4 * j, v.x, v.y, v.z, v.w);
        }
    }
}

// ---------------------------------------------------------------------------
// finalize: mean division with count clipped to >= 1 (vectorized)
// ---------------------------------------------------------------------------
__global__ void finalize_kernel(float* __restrict__ out) {
    int stride = gridDim.x * blockDim.x;
    for (int i = blockIdx.x * blockDim.x + threadIdx.x; i < NNODES * 16; i += stride) {
        float inv = 1.0f / fmaxf(g_cnt[i >> 4], 1.0f);
        float4 v = ((float4*)out)[i];
        v.x *= inv; v.y *= inv; v.z *= inv; v.w *= inv;
        ((float4*)out)[i] = v;
    }
}

// ---------------------------------------------------------------------------
extern "C" void kernel_launch(void* const* d_in, const int* in_sizes, int n_in,
                              void* d_out, int out_size)
{
    const float* x  = (const float*)d_in[0];
    const int*   ei = (const int*)  d_in[1];
    const float* ea = (const float*)d_in[2];
    const float* W1 = (const float*)d_in[3];
    const float* b1 = (const float*)d_in[4];
    const float* W2 = (const float*)d_in[5];
    const float* b2 = (const float*)d_in[6];
    float* out = (float*)d_out;

    const int smem_bytes = SM_WORDS * 4;
    cudaFuncSetAttribute(edge_kernel,
                         cudaFuncAttributeMaxDynamicSharedMemorySize, smem_bytes);

    init_kernel<<<592, 256>>>(out);
    node_gemm_kernel<<<(NNODES + 31) / 32, 256>>>(x, W1);
    edge_kernel<<<NEDGES / EB, 256, smem_bytes>>>(ei, ea, W1, b1, W2, b2, out);
    finalize_kernel<<<592, 256>>>(out);
}

// round 17
// speedup vs baseline: 2.2343x; 1.2869x over previous
#include <cuda_runtime.h>

#define NNODES 50000
#define NEDGES 800000
// channels: IN=64, EDGE=32, OUT=64, d_in = 160

// Scratch (allocation-free rule: __device__ globals)
__device__ float g_AB[(size_t)NNODES * 128];   // [n][0:64]=x@W1a, [64:128]=x@W1b
__device__ float g_H[(size_t)NNODES * 64];     // scatter-summed hidden h
__device__ float g_cnt[NNODES];

// ---------------------------------------------------------------------------
// helpers
// ---------------------------------------------------------------------------
__device__ __forceinline__ unsigned f2tf32(float f) {
    unsigned r;
    asm("cvt.rna.tf32.f32 %0, %1;" : "=r"(r) : "f"(f));
    return r;
}

__device__ __forceinline__ void mma_tf32(float c[4],
                                         unsigned a0, unsigned a1,
                                         unsigned a2, unsigned a3,
                                         unsigned b0, unsigned b1) {
    asm volatile(
        "mma.sync.aligned.m16n8k8.row.col.f32.tf32.tf32.f32 "
        "{%0,%1,%2,%3}, {%4,%5,%6,%7}, {%8,%9}, {%0,%1,%2,%3};"
        : "+f"(c[0]), "+f"(c[1]), "+f"(c[2]), "+f"(c[3])
        : "r"(a0), "r"(a1), "r"(a2), "r"(a3), "r"(b0), "r"(b1));
}

__device__ __forceinline__ void red_add_v4(float* addr, float a, float b,
                                           float c, float d) {
    asm volatile("red.global.add.v4.f32 [%0], {%1, %2, %3, %4};"
                 :: "l"(addr), "f"(a), "f"(b), "f"(c), "f"(d)
                 : "memory");
}

// ---------------------------------------------------------------------------
// init: zero H accumulator + counts (out is fully written by post_gemm)
// ---------------------------------------------------------------------------
__global__ void init_kernel() {
    int stride = gridDim.x * blockDim.x;
    for (int i = blockIdx.x * blockDim.x + threadIdx.x; i < NNODES * 16; i += stride)
        ((float4*)g_H)[i] = make_float4(0.f, 0.f, 0.f, 0.f);
    for (int i = blockIdx.x * blockDim.x + threadIdx.x; i < NNODES; i += stride)
        g_cnt[i] = 0.0f;
}

// ---------------------------------------------------------------------------
// node GEMM (fp32, exact): AB[n][c'] = sum_k x[n][k] * Wn[k][c']
//   Wn[k][c'] = W1[k][c'] (c'<64, row-part) / W1[64+k][c'-64] (col-part)
// ---------------------------------------------------------------------------
__global__ __launch_bounds__(256) void node_gemm_kernel(
    const float* __restrict__ x, const float* __restrict__ W1)
{
    __shared__ float s_x[32 * 65];
    __shared__ float s_W[64 * 128];

    int tid = threadIdx.x;
    int n_base = blockIdx.x * 32;

    for (int idx = tid; idx < 64 * 128; idx += 256) {
        int k = idx >> 7, c = idx & 127;
        s_W[idx] = (c < 64) ? W1[k * 64 + c] : W1[(64 + k) * 64 + (c - 64)];
    }
    for (int idx = tid; idx < 32 * 64; idx += 256) {
        int n = idx >> 6, k = idx & 63;
        int gn = n_base + n;
        s_x[n * 65 + k] = (gn < NNODES) ? x[(size_t)gn * 64 + k] : 0.0f;
    }
    __syncthreads();

    int tr = tid >> 5, tc = tid & 31;
    int n0 = tr * 4, c0 = tc * 4;

    float acc[4][4] = {};
#pragma unroll 16
    for (int k = 0; k < 64; k++) {
        float a[4];
#pragma unroll
        for (int i = 0; i < 4; i++) a[i] = s_x[(n0 + i) * 65 + k];
        float4 b = *(const float4*)&s_W[k * 128 + c0];
#pragma unroll
        for (int i = 0; i < 4; i++) {
            acc[i][0] = fmaf(a[i], b.x, acc[i][0]);
            acc[i][1] = fmaf(a[i], b.y, acc[i][1]);
            acc[i][2] = fmaf(a[i], b.z, acc[i][2]);
            acc[i][3] = fmaf(a[i], b.w, acc[i][3]);
        }
    }
#pragma unroll
    for (int i = 0; i < 4; i++) {
        int gn = n_base + n0 + i;
        if (gn < NNODES) {
            float4 v = make_float4(acc[i][0], acc[i][1], acc[i][2], acc[i][3]);
            *(float4*)&g_AB[(size_t)gn * 128 + c0] = v;
        }
    }
}

// ---------------------------------------------------------------------------
// edge kernel (tf32 GEMM1 only — W2 commutes with the scatter sum and is
// applied once per node in post_gemm_kernel):
//   GEMM1: C = ea @ W1c (K=32)   [tf32, hardware-verified fragment code]
//   h = relu(C + AB[row][0:64] + AB[col][64:128] + b1)   [fp32 exact]
//   scatter: red.global.add.v4 of h into g_H[col], + per-edge count
// 128 edges/block, 256 threads (8 warps, 16 edges/warp). 45 KB static smem.
// ---------------------------------------------------------------------------
#define EB 128                      // edges per block
#define SW1 36                      // stride of [n][k] W1c tile (k<32) and ea
#define SW2 68                      // stride of fp32 h buffer
#define SM_W1C_OFF 0                            // 64*36 u32
#define SM_H_OFF   (64 * SW1)                   // 128*68 (aliases ea 128*36)
#define SM_IDX_OFF (SM_H_OFF + EB * SW2)        // 2*128 ints
#define SM_WORDS   (SM_IDX_OFF + 2 * EB)        // 11264 u32 = 45056 B

__global__ __launch_bounds__(256) void edge_kernel(
    const int*   __restrict__ ei,   // [2*E], row then col
    const float* __restrict__ ea,   // [E,32]
    const float* __restrict__ W1,   // [160,64]
    const float* __restrict__ bias1)// [64]
{
    __shared__ unsigned smem[SM_WORDS];
    unsigned* u_W1c = smem + SM_W1C_OFF;
    unsigned* u_ea  = smem + SM_H_OFF;      // phase 1 alias of h buffer
    float*    f_h   = (float*)(smem + SM_H_OFF);
    int*      s_row = (int*)(smem + SM_IDX_OFF);
    int*      s_col = s_row + EB;

    int tid = threadIdx.x;
    int e_base = blockIdx.x * EB;

    // ---- stage indices + counts ----
    if (tid < EB) {
        s_row[tid] = ei[e_base + tid];
        int c = ei[NEDGES + e_base + tid];
        s_col[tid] = c;
        atomicAdd(&g_cnt[c], 1.0f);
    }
    // ---- stage W1c (rows 128..159 of W1), transposed [n][k], tf32 ----
    for (int idx = tid; idx < 32 * 64; idx += 256) {
        int k = idx >> 6, n = idx & 63;
        u_W1c[n * SW1 + k] = f2tf32(W1[128 * 64 + idx]);
    }
    // ---- stage ea [e][k] tf32 (float4 global reads) ----
    for (int idx4 = tid; idx4 < EB * 8; idx4 += 256) {
        int e = idx4 >> 3, k4 = (idx4 & 7) * 4;
        float4 v = *(const float4*)&ea[(size_t)(e_base + e) * 32 + k4];
        unsigned* p = &u_ea[e * SW1 + k4];
        p[0] = f2tf32(v.x); p[1] = f2tf32(v.y);
        p[2] = f2tf32(v.z); p[3] = f2tf32(v.w);
    }
    __syncthreads();

    int lane = tid & 31;
    int gid = lane >> 2;      // 0..7  (row within tile / col within B tile)
    int tig = lane & 3;       // 0..3  (k within fragment)
    int me0 = (tid >> 5) * 16;  // warp's edge base (8 warps x 16 edges)

    int le1 = me0 + gid;      // this thread's two edge rows
    int le2 = le1 + 8;

    // ---- GEMM1: C1 = ea @ W1c, K=32, acc[nt][4] over 8 n-tiles ----
    float c1[8][4] = {};
#pragma unroll
    for (int k0 = 0; k0 < 32; k0 += 8) {
        unsigned a0 = u_ea[le1 * SW1 + k0 + tig];
        unsigned a1 = u_ea[le2 * SW1 + k0 + tig];
        unsigned a2 = u_ea[le1 * SW1 + k0 + tig + 4];
        unsigned a3 = u_ea[le2 * SW1 + k0 + tig + 4];
#pragma unroll
        for (int nt = 0; nt < 8; nt++) {
            unsigned b0 = u_W1c[(nt * 8 + gid) * SW1 + k0 + tig];
            unsigned b1 = u_W1c[(nt * 8 + gid) * SW1 + k0 + tig + 4];
            mma_tf32(c1[nt], a0, a1, a2, a3, b0, b1);
        }
    }
    __syncthreads();   // all warps done reading u_ea; region becomes f_h

    // ---- epilogue: gather node terms + bias, relu, store fp32 h ----
    {
        int r1 = s_row[le1], r2 = s_row[le2];
        int d1 = s_col[le1], d2 = s_col[le2];
#pragma unroll
        for (int nt = 0; nt < 8; nt++) {
            int col = nt * 8 + 2 * tig;
            float2 bb = *(const float2*)&bias1[col];
            float2 ar1 = *(const float2*)&g_AB[(size_t)r1 * 128 + col];
            float2 ac1 = *(const float2*)&g_AB[(size_t)d1 * 128 + 64 + col];
            float2 ar2 = *(const float2*)&g_AB[(size_t)r2 * 128 + col];
            float2 ac2 = *(const float2*)&g_AB[(size_t)d2 * 128 + 64 + col];
            f_h[le1 * SW2 + col]     = fmaxf(c1[nt][0] + ar1.x + ac1.x + bb.x, 0.f);
            f_h[le1 * SW2 + col + 1] = fmaxf(c1[nt][1] + ar1.y + ac1.y + bb.y, 0.f);
            f_h[le2 * SW2 + col]     = fmaxf(c1[nt][2] + ar2.x + ac2.x + bb.x, 0.f);
            f_h[le2 * SW2 + col + 1] = fmaxf(c1[nt][3] + ar2.y + ac2.y + bb.y, 0.f);
        }
    }
    __syncthreads();

    // ---- scatter h into g_H (8 x red.v4 per thread, 2 threads/edge) ----
    {
        int e = tid >> 1, half = (tid & 1) * 32;
        int dst = s_col[e];
        float* o = &g_H[(size_t)dst * 64 + half];
        const float* src = &f_h[e * SW2 + half];
#pragma unroll
        for (int j = 0; j < 8; j++) {
            float4 v = *(const float4*)&src[4 * j];
            red_add_v4(o + 4 * j, v.x, v.y, v.z, v.w);
        }
    }
}

// ---------------------------------------------------------------------------
// post GEMM (fp32, exact): out[n] = (H[n]/clip(cnt,1)) @ W2 + b2*[cnt>0]
// 32 nodes x 64 cols per block, 256 threads, 4x2 micro-tile
// ---------------------------------------------------------------------------
__global__ __launch_bounds__(256) void post_gemm_kernel(
    const float* __restrict__ W2, const float* __restrict__ b2,
    float* __restrict__ out)
{
    __shared__ float s_H[32 * 65];
    __shared__ float s_W[64 * 64];
    __shared__ float s_has[32];     // 1.0 if cnt>0 else 0.0

    int tid = threadIdx.x;
    int n_base = blockIdx.x * 32;

    for (int idx = tid; idx < 64 * 64; idx += 256)
        s_W[idx] = W2[idx];
    // stage H scaled by 1/clip(cnt)
    for (int idx = tid; idx < 32 * 64; idx += 256) {
        int n = idx >> 6, k = idx & 63;
        int gn = n_base + n;
        float v = 0.0f;
        if (gn < NNODES) {
            float c = g_cnt[gn];
            v = g_H[(size_t)gn * 64 + k] * (1.0f / fmaxf(c, 1.0f));
        }
        s_H[n * 65 + k] = v;
    }
    if (tid < 32) {
        int gn = n_base + tid;
        s_has[tid] = (gn < NNODES && g_cnt[gn] > 0.0f) ? 1.0f : 0.0f;
    }
    __syncthreads();

    int tr = tid >> 5, tc = tid & 31;   // 8 x 32
    int n0 = tr * 4, c0 = tc * 2;

    float acc[4][2] = {};
#pragma unroll 16
    for (int k = 0; k < 64; k++) {
        float a[4];
#pragma unroll
        for (int i = 0; i < 4; i++) a[i] = s_H[(n0 + i) * 65 + k];
        float2 b = *(const float2*)&s_W[k * 64 + c0];
#pragma unroll
        for (int i = 0; i < 4; i++) {
            acc[i][0] = fmaf(a[i], b.x, acc[i][0]);
            acc[i][1] = fmaf(a[i], b.y, acc[i][1]);
        }
    }

    float2 bb = *(const float2*)&b2[c0];
#pragma unroll
    for (int i = 0; i < 4; i++) {
        int gn = n_base + n0 + i;
        if (gn < NNODES) {
            float has = s_has[n0 + i];
            float2 v = make_float2(acc[i][0] + bb.x * has,
                                   acc[i][1] + bb.y * has);
            *(float2*)&out[(size_t)gn * 64 + c0] = v;
        }
    }
}

// ---------------------------------------------------------------------------
extern "C" void kernel_launch(void* const* d_in, const int* in_sizes, int n_in,
                              void* d_out, int out_size)
{
    const float* x  = (const float*)d_in[0];
    const int*   ei = (const int*)  d_in[1];
    const float* ea = (const float*)d_in[2];
    const float* W1 = (const float*)d_in[3];
    const float* b1 = (const float*)d_in[4];
    const float* W2 = (const float*)d_in[5];
    const float* b2 = (const float*)d_in[6];
    float* out = (float*)d_out;

    init_kernel<<<592, 256>>>();
    node_gemm_kernel<<<(NNODES + 31) / 32, 256>>>(x, W1);
    edge_kernel<<<NEDGES / EB, 256>>>(ei, ea, W1, b1);
    post_gemm_kernel<<<(NNODES + 31) / 32, 256>>>(W2, b2, out);
}